// round 5
// baseline (speedup 1.0000x reference)
#include <cuda_runtime.h>

// Problem constants: y (4,1,512,512) fp32, BINS=256, VMIN=0, VMAX=1, SIGMA=30.
#define NB 4
#define HW 262144            // 512*512 pixels per batch
#define FINE 4096            // fine sub-bins (16 per output bin)
#define BINS 256
#define CPB 16               // histogram CTAs per batch
#define HIST_CTAS (NB*CPB)   // 64
#define PIX_PER_CTA (HW/CPB) // 16384
#define TBL 8192             // K table allocation (8176 valid)
#define TOFF 4080            // index offset: q = idx - TOFF, q in [-4080, 4095]
#define KSTEP (30.0f/4096.0f)

__device__ unsigned int g_part[HIST_CTAS][FINE];
__device__ float g_n[NB][FINE];
__device__ float g_K[TBL];
__device__ float g_rows[NB*BINS];

// sigmoid for t <= 0, accurate (small value form)
__device__ __forceinline__ float sneg(float t) {
    float e = expf(t);
    return e / (1.0f + e);
}
// sigma(a1) - sigma(a2), a1 > a2, cancellation-safe
__device__ __forceinline__ float sigdiff(float a1, float a2) {
    if (a2 >= 0.0f) return sneg(-a2) - sneg(-a1);   // both >= 0
    if (a1 <= 0.0f) return sneg(a1) - sneg(a2);     // both <= 0
    return (1.0f - sneg(-a1)) - sneg(a2);           // straddles 0
}

// ---------------------------------------------------------------------------
// K1: fine histogram (per-CTA shared atomics -> partials) + K table build
// ---------------------------------------------------------------------------
__global__ void __launch_bounds__(1024) k_hist(const float* __restrict__ y) {
    int bid = blockIdx.x;
    if (bid < HIST_CTAS) {
        __shared__ unsigned int sh[FINE];
        #pragma unroll
        for (int k = 0; k < FINE/1024; k++) sh[threadIdx.x + k*1024] = 0u;
        __syncthreads();

        const float4* p = (const float4*)(y + (size_t)bid * PIX_PER_CTA);
        #pragma unroll
        for (int k = 0; k < PIX_PER_CTA/4096; k++) {
            float4 v = p[threadIdx.x + k*1024];
            int m0 = min(max((int)(v.x * (float)FINE), 0), FINE-1);
            int m1 = min(max((int)(v.y * (float)FINE), 0), FINE-1);
            int m2 = min(max((int)(v.z * (float)FINE), 0), FINE-1);
            int m3 = min(max((int)(v.w * (float)FINE), 0), FINE-1);
            atomicAdd(&sh[m0], 1u);
            atomicAdd(&sh[m1], 1u);
            atomicAdd(&sh[m2], 1u);
            atomicAdd(&sh[m3], 1u);
        }
        __syncthreads();
        #pragma unroll
        for (int k = 0; k < FINE/1024; k++) {
            int m = threadIdx.x + k*1024;
            g_part[bid][m] = sh[m];
        }
    } else {
        // K table: K[idx] = sigma(s*(q+0.5)) - sigma(s*(q-15.5)), q = idx-TOFF
        int idx = (bid - HIST_CTAS) * 1024 + threadIdx.x;
        if (idx < TBL) {
            if (idx < TOFF + FINE + 1) {   // 8177 > needed 8176; all valid range
                float q = (float)(idx - TOFF);
                float a1 = KSTEP * (q + 0.5f);
                float a2 = KSTEP * (q - 15.5f);
                g_K[idx] = sigdiff(a1, a2);
            } else {
                g_K[idx] = 0.0f;
            }
        }
    }
}

// ---------------------------------------------------------------------------
// K2: merge 16 partials per batch -> float counts
// ---------------------------------------------------------------------------
__global__ void __launch_bounds__(1024) k_merge() {
    int idx = blockIdx.x * 1024 + threadIdx.x;   // 0..16383
    int b = idx >> 12;
    int m = idx & (FINE - 1);
    unsigned int sum = 0;
    #pragma unroll
    for (int c = 0; c < CPB; c++) sum += g_part[b * CPB + c][m];
    g_n[b][m] = (float)sum;
}

// ---------------------------------------------------------------------------
// K3: 1024 correlation rows (b,i): hist = sum_m n[b][m]*K[m-16i]; -> -p log p
//     128 CTAs x 8 warps, one warp per row, n cached in shared.
// ---------------------------------------------------------------------------
__global__ void __launch_bounds__(256) k_rows() {
    __shared__ float sn[FINE];
    int b = blockIdx.x >> 5;              // 32 CTAs per batch
    #pragma unroll
    for (int k = 0; k < FINE/256; k++) {
        int m = threadIdx.x + k*256;
        sn[m] = g_n[b][m];
    }
    __syncthreads();

    int warp = threadIdx.x >> 5;
    int lane = threadIdx.x & 31;
    int i = (blockIdx.x & 31) * 8 + warp; // bin 0..255
    const float* Kp = g_K + (TOFF - 16*i);

    float a0 = 0.f, a1 = 0.f, a2 = 0.f, a3 = 0.f;
    #pragma unroll 8
    for (int t = 0; t < FINE; t += 128) {
        int m0 = lane + t;
        a0 += sn[m0      ] * __ldg(Kp + m0      );
        a1 += sn[m0 +  32] * __ldg(Kp + m0 +  32);
        a2 += sn[m0 +  64] * __ldg(Kp + m0 +  64);
        a3 += sn[m0 +  96] * __ldg(Kp + m0 +  96);
    }
    float acc = (a0 + a1) + (a2 + a3);
    #pragma unroll
    for (int off = 16; off; off >>= 1)
        acc += __shfl_down_sync(0xffffffffu, acc, off);

    if (lane == 0) {
        float p = acc * (1.0f / (float)HW) + 1e-6f;
        g_rows[b * BINS + i] = -p * logf(p);
    }
}

// ---------------------------------------------------------------------------
// K4: deterministic tree reduce of 1024 terms; out = 1/d
// ---------------------------------------------------------------------------
__global__ void __launch_bounds__(256) k_final(float* __restrict__ out) {
    __shared__ float s[256];
    int t = threadIdx.x;
    float v = g_rows[t] + g_rows[t + 256] + g_rows[t + 512] + g_rows[t + 768];
    s[t] = v;
    __syncthreads();
    #pragma unroll
    for (int off = 128; off; off >>= 1) {
        if (t < off) s[t] += s[t + off];
        __syncthreads();
    }
    if (t == 0) out[0] = 1.0f / s[0];
}

extern "C" void kernel_launch(void* const* d_in, const int* in_sizes, int n_in,
                              void* d_out, int out_size) {
    (void)in_sizes; (void)n_in; (void)out_size;
    const float* y = (const float*)d_in[0];
    k_hist<<<HIST_CTAS + TBL/1024, 1024>>>(y);
    k_merge<<<NB * FINE / 1024, 1024>>>();
    k_rows<<<128, 256>>>();
    k_final<<<1, 256>>>((float*)d_out);
}

// round 6
// speedup vs baseline: 1.4400x; 1.4400x over previous
#include <cuda_runtime.h>

// y (4,1,512,512) fp32; BINS=256, VMIN=0, VMAX=1, SIGMA=30.
// Strategy: exact fine histogram (4096 sub-bins) -> hist[b][i] = sum_m n[b][m]*K[m-16i]
// with K a precomputed sigmoid-difference table. Entire pipeline in ONE kernel
// (128 CTAs, single wave) using self-resetting software grid barriers.

#define NB 4
#define HW 262144
#define FINE 4096
#define BINS 256
#define GRID 128
#define CPB 32                    // histogram CTAs per batch
#define PIX_PER_CTA (HW/CPB)      // 8192
#define TBL 8192                  // K table alloc (8176 valid)
#define TOFF 4080                 // K index offset
#define KSTEP (30.0f/4096.0f)
#define NTHR 1024

__device__ unsigned int g_nu[NB][FINE];   // zero at load; re-zeroed after use each call
__device__ float        g_K[TBL];
__device__ float        g_rows[NB*BINS];
__device__ unsigned int g_bar[2];         // barrier counters; self-reset to 0 each call

// sigmoid for t <= 0 (no cancellation)
__device__ __forceinline__ float sneg(float t) {
    float e = expf(t);
    return e / (1.0f + e);
}
// sigma(a1) - sigma(a2), a1 > a2, cancellation-safe
__device__ __forceinline__ float sigdiff(float a1, float a2) {
    if (a2 >= 0.0f) return sneg(-a2) - sneg(-a1);
    if (a1 <= 0.0f) return sneg(a1) - sneg(a2);
    return (1.0f - sneg(-a1)) - sneg(a2);
}

// Two-phase counting grid barrier. Re-entrant across graph replays:
// counter goes 0 -> GRID (arrive) -> 2*GRID (depart) -> reset to 0 by last departer.
// Reset only happens after every CTA has exited its spin, so no lost wakeups.
__device__ __forceinline__ void gridbar(int k) {
    __syncthreads();
    if (threadIdx.x == 0) {
        __threadfence();
        atomicAdd(&g_bar[k], 1u);
        while (*((volatile unsigned int*)&g_bar[k]) < (unsigned)GRID) { }
        unsigned int old = atomicAdd(&g_bar[k], 1u);
        if (old == 2u * GRID - 1u) atomicExch(&g_bar[k], 0u);
        __threadfence();
    }
    __syncthreads();
}

__global__ void __launch_bounds__(NTHR, 1) k_fused(const float* __restrict__ y,
                                                   float* __restrict__ out) {
    __shared__ unsigned int shh[FINE];          // phase1: hist, phase2: reused as float n
    __shared__ float s_part[8][4];
    __shared__ float s_red[NTHR];

    const int tid = threadIdx.x;
    const int cta = blockIdx.x;
    const int b   = cta >> 5;                   // batch 0..3
    const int g   = cta & 31;                   // group within batch

    // ---- K table slice: 64 entries per CTA (covers 8192 total) ----
    if (tid < 64) {
        int idx = cta * 64 + tid;
        float v = 0.0f;
        if (idx < TOFF + FINE) {                // 8176 valid entries
            float q = (float)(idx - TOFF);
            v = sigdiff(KSTEP * (q + 0.5f), KSTEP * (q - 15.5f));
        }
        g_K[idx] = v;
    }

    // ---- Phase 1: per-CTA shared fine histogram ----
    #pragma unroll
    for (int k = 0; k < FINE/NTHR; k++) shh[tid + k*NTHR] = 0u;
    __syncthreads();

    const float4* p = (const float4*)(y + (size_t)b * HW + (size_t)g * PIX_PER_CTA);
    #pragma unroll
    for (int k = 0; k < PIX_PER_CTA/(4*NTHR); k++) {   // 2 iterations
        float4 v = p[tid + k*NTHR];
        atomicAdd(&shh[min(max((int)(v.x * (float)FINE), 0), FINE-1)], 1u);
        atomicAdd(&shh[min(max((int)(v.y * (float)FINE), 0), FINE-1)], 1u);
        atomicAdd(&shh[min(max((int)(v.z * (float)FINE), 0), FINE-1)], 1u);
        atomicAdd(&shh[min(max((int)(v.w * (float)FINE), 0), FINE-1)], 1u);
    }
    __syncthreads();

    // merge into global integer counts (exact, order-independent)
    #pragma unroll
    for (int k = 0; k < FINE/NTHR; k++) {
        int m = tid + k*NTHR;
        unsigned int c = shh[m];
        if (c) atomicAdd(&g_nu[b][m], c);
    }

    gridbar(0);

    // ---- Phase 2: correlation rows. Load this batch's counts as float into shared ----
    float* snf = (float*)shh;
    {
        uint4 u = ((const uint4*)g_nu[b])[tid];         // 1024 x uint4 = 4096
        float4 f = make_float4((float)u.x, (float)u.y, (float)u.z, (float)u.w);
        ((float4*)snf)[tid] = f;
    }
    __syncthreads();

    // 8 rows per CTA, 4 warps per row, 1024 taps per warp (float4 per lane)
    {
        int w = tid >> 5, lane = tid & 31;
        int r = w >> 2, q = w & 3;
        int i = g * 8 + r;                               // output bin
        const float*  np = snf + q * 1024;
        const float4* Kp = (const float4*)(g_K + (TOFF - 16*i) + q * 1024);

        float4 acc = make_float4(0.f, 0.f, 0.f, 0.f);
        #pragma unroll
        for (int it = 0; it < 8; it++) {
            int m = it * 128 + lane * 4;
            float4 nv = *(const float4*)(np + m);
            float4 kv = __ldg(Kp + (m >> 2));
            acc.x += nv.x * kv.x; acc.y += nv.y * kv.y;
            acc.z += nv.z * kv.z; acc.w += nv.w * kv.w;
        }
        float a = (acc.x + acc.y) + (acc.z + acc.w);
        #pragma unroll
        for (int off = 16; off; off >>= 1)
            a += __shfl_down_sync(0xffffffffu, a, off);
        if (lane == 0) s_part[r][q] = a;
    }
    __syncthreads();

    if (tid < 8) {
        float h = (s_part[tid][0] + s_part[tid][1]) + (s_part[tid][2] + s_part[tid][3]);
        float pr = h * (1.0f / (float)HW) + 1e-6f;
        g_rows[b * BINS + g * 8 + tid] = -pr * logf(pr);
    }

    gridbar(1);

    // ---- Phase 3: CTA0 reduces 1024 terms (fixed tree); CTAs 1..16 re-zero counts ----
    if (cta == 0) {
        s_red[tid] = g_rows[tid];
        __syncthreads();
        #pragma unroll
        for (int off = 512; off; off >>= 1) {
            if (tid < off) s_red[tid] += s_red[tid + off];
            __syncthreads();
        }
        if (tid == 0) out[0] = 1.0f / s_red[0];
    } else if (cta <= 16) {
        ((unsigned int*)g_nu)[(cta - 1) * NTHR + tid] = 0u;   // 16*1024 = 16384 entries
    }
}

extern "C" void kernel_launch(void* const* d_in, const int* in_sizes, int n_in,
                              void* d_out, int out_size) {
    (void)in_sizes; (void)n_in; (void)out_size;
    k_fused<<<GRID, NTHR>>>((const float*)d_in[0], (float*)d_out);
}